// round 3
// baseline (speedup 1.0000x reference)
#include <cuda_runtime.h>
#include <cuda_bf16.h>

#define DD 128
#define MAXN 40000

// ---------------- device scratch (allocation-free rule) ----------------
__device__ float g_Ah[MAXN * DD];
__device__ float g_Bh[MAXN * DD];
__device__ float g_Dh[MAXN * DD];
__device__ float g_Eh[MAXN * DD];
__device__ float g_num[MAXN * DD];
__device__ float g_den[MAXN * DD];
__device__ int   g_deg[MAXN];
// transposed weights, bf16 hi/lo split, stored pre-swizzled (blocked SW128-style)
__device__ __align__(16) unsigned char g_Whi[5 * 32768];
__device__ __align__(16) unsigned char g_Wlo[5 * 32768];

// ---------------- smem layout (dynamic) ----------------
#define SM_WHI 0
#define SM_WLO 32768
#define SM_AHI 65536
#define SM_ALO 98304
#define SM_C   131072                      // 128 x 132 f32 staging
#define SMEM_REQ (131072 + 128 * 132 * 4)  // 198656

// ---------------- helpers ----------------
static __device__ __forceinline__ unsigned smem_u32(const void* p) {
    unsigned a;
    asm("{ .reg .u64 t; cvta.to.shared.u64 t, %1; cvt.u32.u64 %0, t; }" : "=r"(a) : "l"(p));
    return a;
}
// blocked swizzled layout for a 128-row x 128-bf16-col tile
// atom = 8 rows x 64 bf16 (1024B); atoms tiled (16 row-groups, 2 col-groups)
static __device__ __forceinline__ unsigned bsw(int row, int col) {
    unsigned off = (unsigned)((((row >> 3) + ((col >> 6) << 4)) << 10)
                              + ((row & 7) << 7) + ((col & 63) << 1));
    return off ^ ((off >> 3) & 0x70);
}
static __device__ __forceinline__ void ldsm_x4(unsigned& r0, unsigned& r1,
                                               unsigned& r2, unsigned& r3, unsigned addr) {
    asm volatile("ldmatrix.sync.aligned.m8n8.x4.shared.b16 {%0,%1,%2,%3}, [%4];"
                 : "=r"(r0), "=r"(r1), "=r"(r2), "=r"(r3) : "r"(addr));
}
static __device__ __forceinline__ void mma_bf16(float c[4], const unsigned a[4],
                                                unsigned b0, unsigned b1) {
    asm volatile("mma.sync.aligned.m16n8k16.row.col.f32.bf16.bf16.f32 "
                 "{%0,%1,%2,%3}, {%4,%5,%6,%7}, {%8,%9}, {%0,%1,%2,%3};"
                 : "+f"(c[0]), "+f"(c[1]), "+f"(c[2]), "+f"(c[3])
                 : "r"(a[0]), "r"(a[1]), "r"(a[2]), "r"(a[3]), "r"(b0), "r"(b1));
}
static __device__ __forceinline__ void red_add_v4(float* p, float4 v) {
    asm volatile("red.global.add.v4.f32 [%0], {%1,%2,%3,%4};"
                 :: "l"(p), "f"(v.x), "f"(v.y), "f"(v.z), "f"(v.w) : "memory");
}

// fp32 tile -> bf16 hi/lo split, written straight into swizzled smem. 256 threads.
template<bool SCALE>
static __device__ __forceinline__ void load_convert_A(
        const float* __restrict__ X, const float* __restrict__ norm,
        int row0, int M, unsigned char* Ahi, unsigned char* Alo) {
    int t = threadIdx.x;
    #pragma unroll
    for (int it = 0; it < 16; it++) {              // 4096 float4 / 256 thr
        int f = t + it * 256;
        int row = f >> 5;                          // 32 float4 per 128-col row
        int col0 = (f & 31) * 4;
        int gr = row0 + row;
        float4 v = make_float4(0.f, 0.f, 0.f, 0.f);
        if (gr < M) {
            v = __ldg((const float4*)(X + (size_t)gr * DD + col0));
            if (SCALE) {
                float nm = __ldg(norm + gr);
                v.x *= nm; v.y *= nm; v.z *= nm; v.w *= nm;
            }
        }
        unsigned hi0, hi1, lo0, lo1;
        asm("cvt.rn.bf16x2.f32 %0, %1, %2;" : "=r"(hi0) : "f"(v.y), "f"(v.x));
        asm("cvt.rn.bf16x2.f32 %0, %1, %2;" : "=r"(hi1) : "f"(v.w), "f"(v.z));
        float h0 = __uint_as_float(hi0 << 16);
        float h1 = __uint_as_float(hi0 & 0xffff0000u);
        float h2 = __uint_as_float(hi1 << 16);
        float h3 = __uint_as_float(hi1 & 0xffff0000u);
        asm("cvt.rn.bf16x2.f32 %0, %1, %2;" : "=r"(lo0) : "f"(v.y - h1), "f"(v.x - h0));
        asm("cvt.rn.bf16x2.f32 %0, %1, %2;" : "=r"(lo1) : "f"(v.w - h3), "f"(v.z - h2));
        unsigned sw = bsw(row, col0);
        *(uint2*)(Ahi + sw) = make_uint2(hi0, hi1);
        *(uint2*)(Alo + sw) = make_uint2(lo0, lo1);
    }
}

// ---------------- HMMA tile: C(128x128) += 3-pass split over K=128 ----------------
static __device__ __forceinline__ void gemm_tile(const unsigned char* sm, float acc[2][8][4]) {
    unsigned aHi = smem_u32(sm + SM_AHI), aLo = smem_u32(sm + SM_ALO);
    unsigned wHi = smem_u32(sm + SM_WHI), wLo = smem_u32(sm + SM_WLO);
    int tid = threadIdx.x, lane = tid & 31, w = tid >> 5;
    int wm = w & 3, wn = w >> 2;
    int m = lane >> 3, lr = lane & 7;
    int aRow = wm * 32 + (m & 1) * 8 + lr;   // + mt*16
    int aCol = (m >> 1) * 8;                 // + k0
    int bRow = wn * 64 + (m >> 1) * 8 + lr;  // + nt*16
    int bCol = (m & 1) * 8;                  // + k0

    #pragma unroll
    for (int pass = 0; pass < 3; pass++) {
        unsigned aB = (pass == 2) ? aLo : aHi;
        unsigned wB = (pass == 1) ? wLo : wHi;
        #pragma unroll
        for (int kk = 0; kk < 8; kk++) {
            int k0 = kk * 16;
            unsigned a[2][4], b[4][4];
            #pragma unroll
            for (int mt = 0; mt < 2; mt++)
                ldsm_x4(a[mt][0], a[mt][1], a[mt][2], a[mt][3],
                        aB + bsw(aRow + mt * 16, k0 + aCol));
            #pragma unroll
            for (int nt = 0; nt < 4; nt++)
                ldsm_x4(b[nt][0], b[nt][1], b[nt][2], b[nt][3],
                        wB + bsw(bRow + nt * 16, k0 + bCol));
            #pragma unroll
            for (int mt = 0; mt < 2; mt++)
                #pragma unroll
                for (int n8 = 0; n8 < 8; n8++)
                    mma_bf16(acc[mt][n8], a[mt], b[n8 >> 1][(n8 & 1) * 2],
                             b[n8 >> 1][(n8 & 1) * 2 + 1]);
        }
    }
}

static __device__ __forceinline__ void stage_C(unsigned char* sm, float acc[2][8][4]) {
    int tid = threadIdx.x, lane = tid & 31, w = tid >> 5;
    int wm = w & 3, wn = w >> 2;
    int r0 = wm * 32 + (lane >> 2), c0 = wn * 64 + 2 * (lane & 3);
    float* C = (float*)(sm + SM_C);
    #pragma unroll
    for (int mt = 0; mt < 2; mt++)
        #pragma unroll
        for (int n8 = 0; n8 < 8; n8++) {
            int r = r0 + mt * 16, c = c0 + n8 * 8;
            *(float2*)(C + (r * 132 + c))       = make_float2(acc[mt][n8][0], acc[mt][n8][1]);
            *(float2*)(C + ((r + 8) * 132 + c)) = make_float2(acc[mt][n8][2], acc[mt][n8][3]);
        }
}

// ---------------- prep: zero accumulators + split/transpose/swizzle weights ----------------
__global__ void prep_kernel(const float* __restrict__ Wa, const float* __restrict__ Wb,
                            const float* __restrict__ Wc, const float* __restrict__ Wd,
                            const float* __restrict__ We, int Nn) {
    int idx = blockIdx.x * blockDim.x + threadIdx.x;
    int q = Nn * (DD / 4);
    if (idx < q) {
        float4 z = make_float4(0.f, 0.f, 0.f, 0.f);
        ((float4*)g_num)[idx] = z;
        ((float4*)g_den)[idx] = z;
    }
    if (idx < Nn) g_deg[idx] = 0;
    if (idx < 5 * 16384) {
        int mm = idx >> 14;
        int rem = idx & 16383;
        int n = rem >> 7, k = rem & 127;
        const float* W = (mm == 0) ? Wa : (mm == 1) ? Wb : (mm == 2) ? Wc : (mm == 3) ? Wd : We;
        float v = W[k * DD + n];                 // transpose: Wt[n][k] = W[k][n]
        __nv_bfloat16 hb = __float2bfloat16(v);
        float hf = __bfloat162float(hb);
        __nv_bfloat16 lb = __float2bfloat16(v - hf);
        unsigned sw = bsw(n, k);
        *(__nv_bfloat16*)(g_Whi + mm * 32768 + sw) = hb;
        *(__nv_bfloat16*)(g_Wlo + mm * 32768 + sw) = lb;
    }
}

// ---------------- node GEMMs: out_y = (h*norm)@W_y + b_y, 4 matrices per CTA ----------------
__global__ __launch_bounds__(256, 1) void node_mma_kernel(
        const float* __restrict__ h, const float* __restrict__ norm,
        const float* __restrict__ ba, const float* __restrict__ bb,
        const float* __restrict__ bd, const float* __restrict__ be, int M) {
    extern __shared__ unsigned char sm[];
    int tid = threadIdx.x;
    int row0 = blockIdx.x * 128;

    load_convert_A<true>(h, norm, row0, M, sm + SM_AHI, sm + SM_ALO);

    const float* biases[4] = {ba, bb, bd, be};
    float* outs[4] = {g_Ah, g_Bh, g_Dh, g_Eh};
    const int widx[4] = {0, 1, 3, 4};

    for (int y = 0; y < 4; y++) {
        {
            const float4* sH = (const float4*)(g_Whi + widx[y] * 32768);
            const float4* sL = (const float4*)(g_Wlo + widx[y] * 32768);
            float4* dH = (float4*)(sm + SM_WHI);
            float4* dL = (float4*)(sm + SM_WLO);
            for (int i = tid; i < 2048; i += 256) { dH[i] = sH[i]; dL[i] = sL[i]; }
        }
        __syncthreads();

        float acc[2][8][4];
        #pragma unroll
        for (int mt = 0; mt < 2; mt++)
            #pragma unroll
            for (int n8 = 0; n8 < 8; n8++)
                #pragma unroll
                for (int q = 0; q < 4; q++) acc[mt][n8][q] = 0.f;

        gemm_tile(sm, acc);
        __syncthreads();
        stage_C(sm, acc);
        __syncthreads();

        int row = tid & 127, half = tid >> 7;
        int gr = row0 + row;
        if (gr < M) {
            const float* C = (const float*)(sm + SM_C) + row * 132 + half * 64;
            const float* bias = biases[y];
            float* out = outs[y];
            #pragma unroll 4
            for (int i = 0; i < 16; i++) {
                int c = half * 64 + i * 4;
                float4 b = __ldg((const float4*)(bias + c));
                float4 v = make_float4(C[i * 4 + 0] + b.x, C[i * 4 + 1] + b.y,
                                       C[i * 4 + 2] + b.z, C[i * 4 + 3] + b.w);
                *(float4*)(out + (size_t)gr * DD + c) = v;
            }
        }
        __syncthreads();
    }
}

// ---------------- edge kernel: Ce GEMM + fused gate/scatter epilogue ----------------
static __device__ __forceinline__ void edge_epilogue(
        const unsigned char* sm, int tile, int E,
        const float* __restrict__ bc, const int* __restrict__ src,
        const int* __restrict__ dst, float* __restrict__ out_e) {
    int tid = threadIdx.x;
    int row = tid & 127, half = tid >> 7;
    int er = tile * 128 + row;
    if (er >= E) return;
    int s = __ldg(src + er), d = __ldg(dst + er);
    const float* C = (const float*)(sm + SM_C) + row * 132 + half * 64;
    const float* Dhp = g_Dh + (size_t)s * DD;
    const float* Ehp = g_Eh + (size_t)d * DD;
    const float* Bhp = g_Bh + (size_t)s * DD;
    float* nup = g_num + (size_t)d * DD;
    float* dep = g_den + (size_t)d * DD;
    float* eop = out_e + (size_t)er * DD;

    #pragma unroll 4
    for (int i = 0; i < 16; i++) {
        int c = half * 64 + i * 4;
        float4 b  = __ldg((const float4*)(bc + c));
        float4 dh = __ldg((const float4*)(Dhp + c));
        float4 eh = __ldg((const float4*)(Ehp + c));
        float4 bh = __ldg((const float4*)(Bhp + c));
        float4 x;
        x.x = C[i * 4 + 0] + b.x + dh.x + eh.x;
        x.y = C[i * 4 + 1] + b.y + dh.y + eh.y;
        x.z = C[i * 4 + 2] + b.z + dh.z + eh.z;
        x.w = C[i * 4 + 3] + b.w + dh.w + eh.w;
        *(float4*)(eop + c) = x;
        float4 sg;
        sg.x = __fdividef(1.f, 1.f + __expf(-x.x));
        sg.y = __fdividef(1.f, 1.f + __expf(-x.y));
        sg.z = __fdividef(1.f, 1.f + __expf(-x.z));
        sg.w = __fdividef(1.f, 1.f + __expf(-x.w));
        float4 nb = make_float4(sg.x * bh.x, sg.y * bh.y, sg.z * bh.z, sg.w * bh.w);
        red_add_v4(nup + c, nb);
        red_add_v4(dep + c, sg);
    }
    if (half == 0) atomicAdd(&g_deg[d], 1);
}

__global__ __launch_bounds__(256, 1) void edge_mma_kernel(
        const float* __restrict__ e, const float* __restrict__ bc,
        const int* __restrict__ src, const int* __restrict__ dst,
        float* __restrict__ out_e, int E) {
    extern __shared__ unsigned char sm[];
    int tid = threadIdx.x;
    {   // Wc (matrix index 2), loaded once for the persistent CTA
        const float4* sH = (const float4*)(g_Whi + 2 * 32768);
        const float4* sL = (const float4*)(g_Wlo + 2 * 32768);
        float4* dH = (float4*)(sm + SM_WHI);
        float4* dL = (float4*)(sm + SM_WLO);
        for (int i = tid; i < 2048; i += 256) { dH[i] = sH[i]; dL[i] = sL[i]; }
    }

    int ntiles = (E + 127) >> 7;
    for (int tile = blockIdx.x; tile < ntiles; tile += gridDim.x) {
        load_convert_A<false>(e, nullptr, tile * 128, E, sm + SM_AHI, sm + SM_ALO);
        __syncthreads();

        float acc[2][8][4];
        #pragma unroll
        for (int mt = 0; mt < 2; mt++)
            #pragma unroll
            for (int n8 = 0; n8 < 8; n8++)
                #pragma unroll
                for (int q = 0; q < 4; q++) acc[mt][n8][q] = 0.f;

        gemm_tile(sm, acc);
        __syncthreads();
        stage_C(sm, acc);
        __syncthreads();
        edge_epilogue(sm, tile, E, bc, src, dst, out_e);
    }
}

// ---------------- finalize ----------------
__global__ void finalize_kernel(const float* __restrict__ h,
                                const float* __restrict__ norm,
                                float* __restrict__ out_h, int Nn) {
    int idx = blockIdx.x * blockDim.x + threadIdx.x;   // float4 index
    int total = Nn * (DD / 4);
    if (idx >= total) return;
    int node = idx >> 5;
    float nm = __ldg(norm + node);
    float4 r;
    if (g_deg[node] > 0) {
        float4 a  = ((const float4*)g_Ah)[idx];
        float4 nu = ((const float4*)g_num)[idx];
        float4 de = ((const float4*)g_den)[idx];
        r.x = (a.x + nu.x / (de.x + 1e-6f)) * nm;
        r.y = (a.y + nu.y / (de.y + 1e-6f)) * nm;
        r.z = (a.z + nu.z / (de.z + 1e-6f)) * nm;
        r.w = (a.w + nu.w / (de.w + 1e-6f)) * nm;
    } else {
        float4 hh = *(const float4*)(h + (size_t)idx * 4);
        float sc = nm * nm;
        r = make_float4(hh.x * sc, hh.y * sc, hh.z * sc, hh.w * sc);
    }
    ((float4*)out_h)[idx] = r;
}

// ---------------- launch ----------------
extern "C" void kernel_launch(void* const* d_in, const int* in_sizes, int n_in,
                              void* d_out, int out_size) {
    const float* h    = (const float*)d_in[0];
    const float* e    = (const float*)d_in[1];
    const float* norm = (const float*)d_in[2];
    const int*   src  = (const int*)d_in[3];
    const int*   dst  = (const int*)d_in[4];
    const float* Wa = (const float*)d_in[5],  *ba = (const float*)d_in[6];
    const float* Wb = (const float*)d_in[7],  *bb = (const float*)d_in[8];
    const float* Wc = (const float*)d_in[9],  *bc = (const float*)d_in[10];
    const float* Wd = (const float*)d_in[11], *bd = (const float*)d_in[12];
    const float* We = (const float*)d_in[13], *be = (const float*)d_in[14];

    int Nn = in_sizes[0] / DD;   // 40000
    int Ee = in_sizes[3];        // 600000

    float* out_h = (float*)d_out;
    float* out_e = out_h + (size_t)Nn * DD;

    static int configured = 0;
    if (!configured) {
        cudaFuncSetAttribute(node_mma_kernel, cudaFuncAttributeMaxDynamicSharedMemorySize, SMEM_REQ);
        cudaFuncSetAttribute(edge_mma_kernel, cudaFuncAttributeMaxDynamicSharedMemorySize, SMEM_REQ);
        configured = 1;
    }

    prep_kernel<<<(Nn * (DD / 4) + 255) / 256, 256>>>(Wa, Wb, Wc, Wd, We, Nn);

    node_mma_kernel<<<(Nn + 127) / 128, 256, SMEM_REQ>>>(h, norm, ba, bb, bd, be, Nn);

    edge_mma_kernel<<<148, 256, SMEM_REQ>>>(e, bc, src, dst, out_e, Ee);

    finalize_kernel<<<(Nn * (DD / 4) + 255) / 256, 256>>>(h, norm, out_h, Nn);
}